// round 12
// baseline (speedup 1.0000x reference)
#include <cuda_runtime.h>
#include <math.h>

#define Nn   4096
#define Sdim 128
#define Ee   131072
#define Kk   8
#define ECAP 128
#define RSQRT_S   0.0883883476483184406f

__device__ float g_P1[Nn*Sdim];
__device__ float g_G [Nn*64];
__device__ float g_Ahv[Nn*96];
__device__ float g_S1[Nn*Sdim];
__device__ float g_hls[Nn*Sdim];
__device__ float g_hlv[Nn*96];
__device__ float g_dv [Nn*96];
__device__ float g_m[Nn];
__device__ int   g_mask[Nn];
__device__ int   g_mscan[Nn+1];
__device__ int   g_midx[Nn];
__device__ float g_Q [Nn*Sdim], g_Kmat[Nn*Sdim];
__device__ float g_U [Nn*Sdim], g_Vv  [Nn*Sdim];
__device__ unsigned g_adj[(size_t)Nn*Nn/32];
__device__ float g_w3sum[Sdim];
__device__ float g_satB;                 // min v with sigf(v)==1.0f
// bucketized real-edge CSR
__device__ int   g_ecnt[Nn];
__device__ int   g_esrc[Nn*ECAP];
__device__ float g_eln [Nn*ECAP];
__device__ float g_edir[Nn*ECAP*3];
// virtual edges
__device__ int   g_nv;
__device__ int   g_vsrc[Nn*Kk], g_vdst[Nn*Kk];
__device__ float g_vln[Nn*Kk], g_vdir[Nn*Kk*3], g_vsc[Nn*Kk];
__device__ int g_vcnt[Nn], g_voff[Nn+1], g_vcur[Nn], g_vcsr[Nn*Kk];

__device__ __forceinline__ float sigf(float x){
    return 1.0f/(1.0f+expf(-x));
}

// ---- prep init ----
__global__ void k_initPrep(const float* __restrict__ Wa1){
    int i=blockIdx.x*blockDim.x+threadIdx.x, st=gridDim.x*blockDim.x;
    for(size_t q=i;q<(size_t)Nn*Nn/32;q+=st) g_adj[q]=0u;
    for(int q=i;q<Nn;q+=st){ g_ecnt[q]=0; g_vcnt[q]=0; }
    if(i==0){
        g_nv=0;
        unsigned lo=0x3F800000u, hi=0x41A00000u;
        while(lo<hi){
            unsigned mid=lo+((hi-lo)>>1);
            if(sigf(__uint_as_float(mid))==1.0f) hi=mid; else lo=mid+1u;
        }
        g_satB=__uint_as_float(lo);
    }
    if(blockIdx.x==0 && threadIdx.x<128){
        int c=threadIdx.x; float s=0.f;
        for(int r=0;r<128;r++) s+=Wa1[(size_t)(256+r)*128+c];
        g_w3sum[c]=s;
    }
}
__global__ void k_zeroA(float* __restrict__ A, const float* __restrict__ pos,
                        float* __restrict__ out_pos){
    size_t i=(size_t)(blockIdx.x*blockDim.x+threadIdx.x), st=(size_t)gridDim.x*blockDim.x;
    float4 z=make_float4(0.f,0.f,0.f,0.f);
    for(size_t q=i;q<(size_t)Nn*Nn/4;q+=st) ((float4*)A)[q]=z;
    if(i<Nn*3) out_pos[i]=pos[i];
}

// one-pass edge prep: adjacency bit + bucket insert + per-edge features
__global__ void k_csrfillD(const int* __restrict__ ei, const float* __restrict__ pos){
    int e=blockIdx.x*blockDim.x+threadIdx.x; if(e>=Ee) return;
    int s=ei[e], d=ei[Ee+e];
    size_t bit=(size_t)s*Nn+d;
    atomicOr(&g_adj[bit>>5],1u<<(bit&31));
    int r=atomicAdd(&g_ecnt[d],1);
    if(r>=ECAP) return;      // statistically unreachable (17+ sigma)
    int p=d*ECAP+r;
    float vx=pos[s*3]-pos[d*3], vy=pos[s*3+1]-pos[d*3+1], vz=pos[s*3+2]-pos[d*3+2];
    float ln=sqrtf(vx*vx+vy*vy+vz*vz);
    float inv = ln>1e-12f ? 1.f/ln : 0.f;
    g_esrc[p]=s; g_eln[p]=ln;
    g_edir[p*3]=vx*inv; g_edir[p*3+1]=vy*inv; g_edir[p*3+2]=vz*inv;
}

// shfl-based exclusive scan of 4096 ints. MODE: 1=mask(+midx), 2=virtual
template<int MODE>
__global__ void k_scan4096(){
    const int* in  = (MODE==1)? g_mask : g_vcnt;
    int*       out = (MODE==1)? g_mscan: g_voff;
    int*       cur = (MODE==1)? (int*)0: g_vcur;
    int t=threadIdx.x, lane=t&31, wid=t>>5;
    int b=t*4;
    int a0=in[b],a1=in[b+1],a2=in[b+2],a3=in[b+3];
    int s=a0+a1+a2+a3;
    int v=s;
    #pragma unroll
    for(int off=1;off<32;off<<=1){ int u=__shfl_up_sync(~0u,v,off); if(lane>=off) v+=u; }
    __shared__ int wsum[32];
    if(lane==31) wsum[wid]=v;
    __syncthreads();
    if(wid==0){
        int w=wsum[lane];
        #pragma unroll
        for(int off=1;off<32;off<<=1){ int u=__shfl_up_sync(~0u,w,off); if(lane>=off) w+=u; }
        wsum[lane]=w;
    }
    __syncthreads();
    int base=(wid>0)?wsum[wid-1]:0;
    int excl=base+v-s;
    int o0=excl,o1=excl+a0,o2=o1+a1,o3=o2+a2;
    out[b]=o0;out[b+1]=o1;out[b+2]=o2;out[b+3]=o3;
    if(cur){cur[b]=o0;cur[b+1]=o1;cur[b+2]=o2;cur[b+3]=o3;}
    if(MODE==1){
        if(a0) g_midx[o0]=b;
        if(a1) g_midx[o1]=b+1;
        if(a2) g_midx[o2]=b+2;
        if(a3) g_midx[o3]=b+3;
    }
    if(t==1023) out[4096]=o3+a3;
}

// ---- batched SGEMM ----
// epi: 0 plain, 1 relu, 2 C=D+AB, 3 blend, 5 store + Ahv(D=hv),
//      6 master MLP (store-free)
struct GDesc { const float* A; const float* B; float* C; const float* D;
               const float* E; const float* E2; float* F; int ncol; int epi; };
struct GPack { GDesc d[5]; };
__global__ void k_mgemm(GPack p){
    GDesc g=p.d[blockIdx.z];
    int nblk=g.ncol>>6;
    if((int)blockIdx.x>=nblk) return;
    const int BM=64, BN=64, KB=16;
    __shared__ __align__(16) float As[KB][BM];
    __shared__ __align__(16) float Bs[KB][BN];
    int tid=threadIdx.x;
    int tx=tid%16, ty=tid/16;
    int row0=blockIdx.y*BM, col0=blockIdx.x*BN;
    const float* A=g.A; const float* B=g.B; int ncol=g.ncol;
    float acc[4][4]={};
    for(int kk=0;kk<128;kk+=KB){
        {
            int lin=tid*4; int m=lin/KB; int k=lin%KB;
            float4 a=*(const float4*)&A[(size_t)(row0+m)*128 + kk + k];
            As[k][m]=a.x; As[k+1][m]=a.y; As[k+2][m]=a.z; As[k+3][m]=a.w;
        }
        {
            int lin=tid*4; int k=lin/BN; int n=lin%BN;
            float4 b=*(const float4*)&B[(size_t)(kk+k)*ncol + col0 + n];
            *(float4*)&Bs[k][n]=b;
        }
        __syncthreads();
        #pragma unroll
        for(int k=0;k<KB;k++){
            float4 av=*(const float4*)&As[k][ty*4];
            float4 bv=*(const float4*)&Bs[k][tx*4];
            float a[4]={av.x,av.y,av.z,av.w};
            float bb[4]={bv.x,bv.y,bv.z,bv.w};
            #pragma unroll
            for(int i=0;i<4;i++)
                #pragma unroll
                for(int j=0;j<4;j++) acc[i][j]+=a[i]*bb[j];
        }
        __syncthreads();
    }
    int epi=g.epi;
    if(epi==6){
        float m2w[4];
        #pragma unroll
        for(int j=0;j<4;j++) m2w[j]=g.E[col0+tx*4+j];
        #pragma unroll
        for(int i=0;i<4;i++){
            float part=0.f;
            #pragma unroll
            for(int j=0;j<4;j++){
                float v=fmaxf(acc[i][j]+g.D[col0+tx*4+j],0.f);
                part+=v*m2w[j];
            }
            #pragma unroll
            for(int off=8;off;off>>=1) part+=__shfl_down_sync(~0u,part,off,16);
            if(tx==0){
                int r=row0+ty*4+i;
                float mm=sigf(part+g.E2[0]);
                g_m[r]=mm; g_mask[r]=(mm>0.5f)?1:0; g.F[r]=mm;
            }
        }
        return;
    }
    #pragma unroll
    for(int i=0;i<4;i++){
        int r=row0+ty*4+i;
        float c1=0.f,c2=1.f;
        if(epi==3){ float mm=g_m[r]; float mk=g_mask[r]?mm:0.f; c2=mk; c1=(1.f-mm)+mk; }
        #pragma unroll
        for(int j=0;j<4;j++){
            int col=col0+tx*4+j;
            size_t ci=(size_t)r*ncol+col;
            float v=acc[i][j];
            if(epi==1) v=fmaxf(v,0.f);
            else if(epi==2) v+=g.D[ci];
            else if(epi==3) v=c2*v + c1*g.D[ci];
            g.C[ci]=v;
            if(epi==5 && col<32){
                const float* hv=g.D;
                g_Ahv[(size_t)r*96+col*3+0]=hv[(size_t)r*96+col*3+0]*v;
                g_Ahv[(size_t)r*96+col*3+1]=hv[(size_t)r*96+col*3+1]*v;
                g_Ahv[(size_t)r*96+col*3+2]=hv[(size_t)r*96+col*3+2]*v;
            }
        }
    }
}

__global__ void k_accum1(const float* __restrict__ hv){
    int d=blockIdx.x, t=threadIdx.x;
    float aS=0.f,aV=0.f;
    int vv=t/3, cc=t-vv*3;
    int cnt=g_ecnt[d]; if(cnt>ECAP) cnt=ECAP;
    int base=d*ECAP;
    for(int p=base;p<base+cnt;p++){
        int s=g_esrc[p];
        float ln=g_eln[p];
        aS += ln*g_P1[(size_t)s*128+t];
        if(t<96){
            aV += g_Ahv[s*96+t] + g_edir[p*3+cc]*g_G[s*64+32+vv];
        }
    }
    g_S1[(size_t)d*128+t]=aS;
    if(t<96) g_hlv[d*96+t]=hv[d*96+t]+aV;
}

// ---- fused selection: warp per master row, ascending-index early-stop ----
// fast path: first 8 allowed cols with saturated sigmoid (value==1.0f > 0.55)
// fallback (row exhausted with <8): exact sigf lexicographic top-8.
__global__ void k_seltop(const float* __restrict__ pos, float* __restrict__ Aout){
    int nm=g_mscan[Nn];
    int w=(blockIdx.x*blockDim.x+threadIdx.x)>>5;
    int lane=threadIdx.x&31;
    if(w>=nm) return;
    int i=w, ni=g_midx[i];
    float4 q=((const float4*)&g_Q[(size_t)ni*128])[lane];
    float B=g_satB;
    int sel[8]; int found=0;
    for(int j0=0;j0<nm && found<8;j0+=2){
        float dt0=0.f,dt1=0.f;
        int j1=j0+1;
        bool ok0=(j0!=i);
        bool ok1=(j1<nm)&&(j1!=i);
        int n0=0,n1=0;
        if(ok0){
            n0=g_midx[j0];
            size_t bit=(size_t)ni*Nn+n0;
            if((g_adj[bit>>5]>>(bit&31))&1u) ok0=false;
        }
        if(ok1){
            n1=g_midx[j1];
            size_t bit=(size_t)ni*Nn+n1;
            if((g_adj[bit>>5]>>(bit&31))&1u) ok1=false;
        }
        if(ok0){
            float4 k=((const float4*)&g_Kmat[(size_t)n0*128])[lane];
            dt0=q.x*k.x+q.y*k.y+q.z*k.z+q.w*k.w;
        }
        if(ok1){
            float4 k=((const float4*)&g_Kmat[(size_t)n1*128])[lane];
            dt1=q.x*k.x+q.y*k.y+q.z*k.z+q.w*k.w;
        }
        #pragma unroll
        for(int off=16;off;off>>=1){
            dt0+=__shfl_xor_sync(~0u,dt0,off);
            dt1+=__shfl_xor_sync(~0u,dt1,off);
        }
        if(ok0 && dt0*RSQRT_S>=B && found<8) sel[found++]=j0;
        if(ok1 && dt1*RSQRT_S>=B && found<8) sel[found++]=j1;
    }
    if(found==8){
        if(lane<8){
            int nj=g_midx[sel[lane]];
            int slot=atomicAdd(&g_nv,1);
            atomicAdd(&g_vcnt[nj],1);
            float vx=pos[ni*3]-pos[nj*3], vy=pos[ni*3+1]-pos[nj*3+1], vz=pos[ni*3+2]-pos[nj*3+2];
            float ln=sqrtf(vx*vx+vy*vy+vz*vz);
            float inv= ln>1e-12f ? 1.f/ln : 0.f;
            g_vsrc[slot]=ni; g_vdst[slot]=nj; g_vln[slot]=ln;
            g_vdir[slot*3]=vx*inv; g_vdir[slot*3+1]=vy*inv; g_vdir[slot*3+2]=vz*inv;
            Aout[(size_t)ni*Nn+nj]=1.0f;
        }
        return;
    }
    // ---- exact fallback: full-row lexicographic top-8 on sigf values ----
    float tv[8]; int tj[8];
    #pragma unroll
    for(int q8=0;q8<8;q8++){ tv[q8]=-INFINITY; tj[q8]=0x40000000; }
    for(int j=0;j<nm;j++){
        if(j==i) continue;
        int nj=g_midx[j];
        size_t bit=(size_t)ni*Nn+nj;
        if((g_adj[bit>>5]>>(bit&31))&1u) continue;
        float4 k=((const float4*)&g_Kmat[(size_t)nj*128])[lane];
        float dt=q.x*k.x+q.y*k.y+q.z*k.z+q.w*k.w;
        #pragma unroll
        for(int off=16;off;off>>=1) dt+=__shfl_xor_sync(~0u,dt,off);
        float v=sigf(dt*RSQRT_S);
        if(v>tv[7] || (v==tv[7] && j<tj[7])){
            int p=7;
            while(p>0 && (v>tv[p-1] || (v==tv[p-1]&&j<tj[p-1]))){
                tv[p]=tv[p-1]; tj[p]=tj[p-1]; p--;
            }
            tv[p]=v; tj[p]=j;
        }
    }
    if(lane<8){
        float v=tv[lane];
        if(v>0.55f){
            int nj=g_midx[tj[lane]];
            int slot=atomicAdd(&g_nv,1);
            atomicAdd(&g_vcnt[nj],1);
            float vx=pos[ni*3]-pos[nj*3], vy=pos[ni*3+1]-pos[nj*3+1], vz=pos[ni*3+2]-pos[nj*3+2];
            float ln=sqrtf(vx*vx+vy*vy+vz*vz);
            float inv= ln>1e-12f ? 1.f/ln : 0.f;
            g_vsrc[slot]=ni; g_vdst[slot]=nj; g_vln[slot]=ln;
            g_vdir[slot*3]=vx*inv; g_vdir[slot*3+1]=vy*inv; g_vdir[slot*3+2]=vz*inv;
            Aout[(size_t)ni*Nn+nj]=1.0f;
        }
    }
}

// vscore: MLP score per virtual edge + CSR insert
__global__ void k_vscore(const float* __restrict__ ba1, const float* __restrict__ Wa2,
                         const float* __restrict__ ba2){
    int slot=blockIdx.x; if(slot>=g_nv) return;
    int t=threadIdx.x;
    int vs=g_vsrc[slot], vd=g_vdst[slot]; float ln=g_vln[slot];
    if(t==0){
        int p=atomicAdd(&g_vcur[vd],1);
        g_vcsr[p]=slot;
    }
    float h=g_U[(size_t)vs*128+t]+g_Vv[(size_t)vd*128+t]+ln*g_w3sum[t]+ba1[t];
    h=fmaxf(h,0.f)*Wa2[t];
    #pragma unroll
    for(int off=16;off;off>>=1) h+=__shfl_down_sync(~0u,h,off);
    __shared__ float ws[4];
    if((t&31)==0) ws[t>>5]=h;
    __syncthreads();
    if(t==0) g_vsc[slot]=ws[0]+ws[1]+ws[2]+ws[3]+ba2[0];
}

// real-edge half of hierarchical accumulation (s2, overlapped)
__global__ void k_accum2r(){
    int d=blockIdx.x, t=threadIdx.x;
    if(!g_mask[d]) return;
    float aS=0.f,aV=0.f;
    int vv=t/3, cc=t-vv*3;
    int cnt=g_ecnt[d]; if(cnt>ECAP) cnt=ECAP;
    int base=d*ECAP;
    for(int p=base;p<base+cnt;p++){
        int s=g_esrc[p];
        if(!g_mask[s]) continue;
        float ln=g_eln[p];
        aS += ln*g_P1[(size_t)s*128+t];
        if(t<96){
            aV += g_Ahv[s*96+t] + g_edir[p*3+cc]*g_G[s*64+32+vv];
        }
    }
    g_S1[(size_t)d*128+t]=aS;
    if(t<96) g_dv[d*96+t]=aV;
}

// virtual-edge add-on with per-dst local softmax
__global__ void k_accum2v(){
    int d=blockIdx.x, t=threadIdx.x, lane=t&31;
    int beg=g_voff[d], end=g_voff[d+1];
    if(beg==end) return;
    __shared__ float smx, sden;
    if(t<32){
        float mx=-INFINITY;
        for(int q=beg+lane;q<end;q+=32) mx=fmaxf(mx,g_vsc[g_vcsr[q]]);
        #pragma unroll
        for(int off=16;off;off>>=1) mx=fmaxf(mx,__shfl_down_sync(~0u,mx,off));
        mx=__shfl_sync(~0u,mx,0);
        float den=0.f;
        for(int q=beg+lane;q<end;q+=32) den+=expf(g_vsc[g_vcsr[q]]-mx);
        #pragma unroll
        for(int off=16;off;off>>=1) den+=__shfl_down_sync(~0u,den,off);
        if(lane==0){ smx=mx; sden=fmaxf(den,1e-9f); }
    }
    __syncthreads();
    float mx=smx, invden=1.f/sden;
    float aS=0.f,aV=0.f;
    int vv=t/3, cc=t-vv*3;
    for(int q=beg;q<end;q++){
        int sl=g_vcsr[q]; int s=g_vsrc[sl];
        float w=expf(g_vsc[sl]-mx)*invden, ln=g_vln[sl];
        aS += ln*w*g_P1[(size_t)s*128+t];
        if(t<96){
            float dir=g_vdir[sl*3+cc]*w;
            aV += g_Ahv[s*96+t] + dir*g_G[s*64+32+vv];
        }
    }
    g_S1[(size_t)d*128+t]+=aS;
    if(t<96) g_dv[d*96+t]+=aV;
}

__global__ void k_finalv(float* __restrict__ out_v){
    int i=blockIdx.x*blockDim.x+threadIdx.x;
    if(i<Nn*96){
        int n=i/96;
        float mm=g_m[n]; float mk=g_mask[n]?mm:0.f;
        out_v[i]=g_hlv[i]*((1.f-mm)+mk)+mk*g_dv[i];
    }
}

extern "C" void kernel_launch(void* const* d_in, const int* in_sizes, int n_in,
                              void* d_out, int out_size){
    const float* h_s =(const float*)d_in[0];
    const float* h_v =(const float*)d_in[1];
    const float* pos =(const float*)d_in[2];
    const int*   ei  =(const int*)  d_in[3];
    const float* W1  =(const float*)d_in[5];
    const float* Wg  =(const float*)d_in[6];
    const float* W2  =(const float*)d_in[7];
    const float* Wm1 =(const float*)d_in[8];
    const float* bm1 =(const float*)d_in[9];
    const float* Wm2 =(const float*)d_in[10];
    const float* bm2 =(const float*)d_in[11];
    const float* Wq  =(const float*)d_in[12];
    const float* Wk  =(const float*)d_in[13];
    const float* Wa1 =(const float*)d_in[14];
    const float* ba1 =(const float*)d_in[15];
    const float* Wa2 =(const float*)d_in[16];
    const float* ba2 =(const float*)d_in[17];

    float *P1,*G,*S1,*HLS,*Q,*KM,*U,*VV,*HLV;
    cudaGetSymbolAddress((void**)&P1, g_P1);
    cudaGetSymbolAddress((void**)&G,  g_G);
    cudaGetSymbolAddress((void**)&S1, g_S1);
    cudaGetSymbolAddress((void**)&HLS,g_hls);
    cudaGetSymbolAddress((void**)&Q,  g_Q);
    cudaGetSymbolAddress((void**)&KM, g_Kmat);
    cudaGetSymbolAddress((void**)&U,  g_U);
    cudaGetSymbolAddress((void**)&VV, g_Vv);
    cudaGetSymbolAddress((void**)&HLV,g_hlv);

    float* out     =(float*)d_out;
    float* out_hfs = out;
    float* out_hfv = out_hfs + (size_t)Nn*Sdim;
    float* out_pos = out_hfv + (size_t)Nn*96;
    float* out_A   = out_pos + (size_t)Nn*3;
    float* out_m   = out_A   + (size_t)Nn*Nn;

    static cudaStream_t s1=0, s2=0;
    static cudaEvent_t evRoot=0, evPrep=0, evZero=0, evHLS=0, evGemmB=0,
                       evScan1=0, evAcc2r=0, evAcc2v=0, evFin=0;
    if(!s1){
        cudaStreamCreateWithFlags(&s1,cudaStreamNonBlocking);
        cudaStreamCreateWithFlags(&s2,cudaStreamNonBlocking);
        cudaEventCreateWithFlags(&evRoot,cudaEventDisableTiming);
        cudaEventCreateWithFlags(&evPrep,cudaEventDisableTiming);
        cudaEventCreateWithFlags(&evZero,cudaEventDisableTiming);
        cudaEventCreateWithFlags(&evHLS,cudaEventDisableTiming);
        cudaEventCreateWithFlags(&evGemmB,cudaEventDisableTiming);
        cudaEventCreateWithFlags(&evScan1,cudaEventDisableTiming);
        cudaEventCreateWithFlags(&evAcc2r,cudaEventDisableTiming);
        cudaEventCreateWithFlags(&evAcc2v,cudaEventDisableTiming);
        cudaEventCreateWithFlags(&evFin,cudaEventDisableTiming);
    }

    cudaEventRecord(evRoot,0);
    cudaStreamWaitEvent(s1,evRoot,0);
    cudaStreamWaitEvent(s2,evRoot,0);

    // s1: adjacency + bucketized edge features (one pass)
    k_initPrep<<<512,256,0,s1>>>(Wa1);
    k_csrfillD<<<(Ee+255)/256,256,0,s1>>>(ei,pos);
    cudaEventRecord(evPrep,s1);

    // s2: zero A_virtual + pos copy
    k_zeroA<<<1024,256,0,s2>>>(out_A,pos,out_pos);
    cudaEventRecord(evZero,s2);

    // main: pass-1 GEMMs
    {
        GPack p{};
        p.d[0]={h_s,W1,P1,nullptr,nullptr,nullptr,nullptr,128,1};
        p.d[1]={h_s,Wg,G, h_v,    nullptr,nullptr,nullptr, 64,5};
        k_mgemm<<<dim3(2,64,2),256>>>(p);
    }
    cudaStreamWaitEvent(0,evPrep,0);
    k_accum1<<<Nn,128>>>(h_v);
    {
        GPack p{};
        p.d[0]={S1,W2,HLS,h_s,nullptr,nullptr,nullptr,128,2};
        k_mgemm<<<dim3(2,64,1),256>>>(p);
    }
    cudaEventRecord(evHLS,0);

    // s1: master MLP (store-free) + mask scan — concurrent with Q/K/U/V pack
    cudaStreamWaitEvent(s1,evHLS,0);
    {
        GPack p{};
        p.d[0]={HLS,Wm1,nullptr,bm1,Wm2,bm2,out_m,64,6};
        k_mgemm<<<dim3(1,64,1),256,0,s1>>>(p);
    }
    k_scan4096<1><<<1,1024,0,s1>>>();
    cudaEventRecord(evScan1,s1);

    // s2: pass-2 backbone GEMMs
    cudaStreamWaitEvent(s2,evHLS,0);
    {
        GPack p{};
        p.d[0]={HLS,W1,P1,nullptr,nullptr,nullptr,nullptr,128,1};
        p.d[1]={HLS,Wg,G, HLV,    nullptr,nullptr,nullptr, 64,5};
        k_mgemm<<<dim3(2,64,2),256,0,s2>>>(p);
    }
    cudaEventRecord(evGemmB,s2);

    // main: Q/K/U/V projections
    {
        GPack p{};
        p.d[0]={HLS,Wq,          Q,  nullptr,nullptr,nullptr,nullptr,128,0};
        p.d[1]={HLS,Wk,          KM, nullptr,nullptr,nullptr,nullptr,128,0};
        p.d[2]={HLS,Wa1,         U,  nullptr,nullptr,nullptr,nullptr,128,0};
        p.d[3]={HLS,Wa1+128*128, VV, nullptr,nullptr,nullptr,nullptr,128,0};
        k_mgemm<<<dim3(2,64,4),256>>>(p);
    }
    cudaStreamWaitEvent(0,evScan1,0);
    cudaStreamWaitEvent(0,evZero,0);
    k_seltop<<<Nn/8,256>>>(pos,out_A);     // fused attention+topk (early-stop)
    k_scan4096<2><<<1,1024>>>();
    k_vscore<<<Nn*Kk,128>>>(ba1,Wa2,ba2);

    // s2: real-edge accum overlapped
    cudaStreamWaitEvent(s2,evScan1,0);
    k_accum2r<<<Nn,128,0,s2>>>();
    cudaEventRecord(evAcc2r,s2);

    // main: virtual add-on, then final GEMM
    cudaStreamWaitEvent(0,evAcc2r,0);
    k_accum2v<<<Nn,128>>>();
    cudaEventRecord(evAcc2v,0);

    // s2: vector blend in parallel with final scalar GEMM
    cudaStreamWaitEvent(s2,evAcc2v,0);
    k_finalv<<<(Nn*96+255)/256,256,0,s2>>>(out_hfv);
    cudaEventRecord(evFin,s2);
    {
        GPack p{};
        p.d[0]={S1,W2,out_hfs,HLS,nullptr,nullptr,nullptr,128,3};
        k_mgemm<<<dim3(2,64,1),256>>>(p);
    }
    cudaStreamWaitEvent(0,evFin,0);
}

// round 13
// speedup vs baseline: 2.5907x; 2.5907x over previous
#include <cuda_runtime.h>
#include <math.h>

#define Nn   4096
#define Sdim 128
#define Ee   131072
#define Kk   8
#define ECAP 128
#define RSQRT_S   0.0883883476483184406f

__device__ float g_P1[Nn*Sdim];
__device__ float g_G [Nn*64];
__device__ float g_Ahv[Nn*96];
__device__ float g_S1[Nn*Sdim];
__device__ float g_hls[Nn*Sdim];
__device__ float g_hlv[Nn*96];
__device__ float g_dv [Nn*96];
__device__ float g_m[Nn];
__device__ int   g_mask[Nn];
__device__ int   g_mscan[Nn+1];
__device__ int   g_midx[Nn];
__device__ float g_Q [Nn*Sdim], g_Kmat[Nn*Sdim];
__device__ float g_U [Nn*Sdim], g_Vv  [Nn*Sdim];
__device__ unsigned g_adj[(size_t)Nn*Nn/32];
__device__ float g_att[(size_t)Nn*Nn];   // raw scaled logits (compact nm x nm)
__device__ float g_w3sum[Sdim];
__device__ float g_satB;
// bucketized real-edge storage
__device__ int   g_ecnt[Nn];
__device__ int   g_esrc[Nn*ECAP];
__device__ float g_eln [Nn*ECAP];
__device__ float g_edir[Nn*ECAP*3];
// virtual edges
__device__ int   g_nv;
__device__ int   g_vsrc[Nn*Kk], g_vdst[Nn*Kk];
__device__ float g_vln[Nn*Kk], g_vdir[Nn*Kk*3], g_vsc[Nn*Kk];
__device__ int g_vcnt[Nn], g_voff[Nn+1], g_vcur[Nn], g_vcsr[Nn*Kk];

__device__ __forceinline__ float sigf(float x){
    return 1.0f/(1.0f+expf(-x));
}

// ---- prep init ----
__global__ void k_initPrep(const float* __restrict__ Wa1){
    int i=blockIdx.x*blockDim.x+threadIdx.x, st=gridDim.x*blockDim.x;
    for(size_t q=i;q<(size_t)Nn*Nn/32;q+=st) g_adj[q]=0u;
    for(int q=i;q<Nn;q+=st){ g_ecnt[q]=0; g_vcnt[q]=0; }
    if(i==0){
        g_nv=0;
        unsigned lo=0x3F800000u, hi=0x41A00000u;
        while(lo<hi){
            unsigned mid=lo+((hi-lo)>>1);
            if(sigf(__uint_as_float(mid))==1.0f) hi=mid; else lo=mid+1u;
        }
        g_satB=__uint_as_float(lo);
    }
    if(blockIdx.x==0 && threadIdx.x<128){
        int c=threadIdx.x; float s=0.f;
        for(int r=0;r<128;r++) s+=Wa1[(size_t)(256+r)*128+c];
        g_w3sum[c]=s;
    }
}
__global__ void k_zeroA(float* __restrict__ A, const float* __restrict__ pos,
                        float* __restrict__ out_pos){
    size_t i=(size_t)(blockIdx.x*blockDim.x+threadIdx.x), st=(size_t)gridDim.x*blockDim.x;
    float4 z=make_float4(0.f,0.f,0.f,0.f);
    for(size_t q=i;q<(size_t)Nn*Nn/4;q+=st) ((float4*)A)[q]=z;
    if(i<Nn*3) out_pos[i]=pos[i];
}

// one-pass edge prep: adjacency bit + bucket insert + per-edge features
__global__ void k_csrfillD(const int* __restrict__ ei, const float* __restrict__ pos){
    int e=blockIdx.x*blockDim.x+threadIdx.x; if(e>=Ee) return;
    int s=ei[e], d=ei[Ee+e];
    size_t bit=(size_t)s*Nn+d;
    atomicOr(&g_adj[bit>>5],1u<<(bit&31));
    int r=atomicAdd(&g_ecnt[d],1);
    if(r>=ECAP) return;      // >17 sigma; unreachable
    int p=d*ECAP+r;
    float vx=pos[s*3]-pos[d*3], vy=pos[s*3+1]-pos[d*3+1], vz=pos[s*3+2]-pos[d*3+2];
    float ln=sqrtf(vx*vx+vy*vy+vz*vz);
    float inv = ln>1e-12f ? 1.f/ln : 0.f;
    g_esrc[p]=s; g_eln[p]=ln;
    g_edir[p*3]=vx*inv; g_edir[p*3+1]=vy*inv; g_edir[p*3+2]=vz*inv;
}

// shfl-based exclusive scan of 4096 ints. MODE: 1=mask(+midx), 2=virtual
template<int MODE>
__global__ void k_scan4096(){
    const int* in  = (MODE==1)? g_mask : g_vcnt;
    int*       out = (MODE==1)? g_mscan: g_voff;
    int*       cur = (MODE==1)? (int*)0: g_vcur;
    int t=threadIdx.x, lane=t&31, wid=t>>5;
    int b=t*4;
    int a0=in[b],a1=in[b+1],a2=in[b+2],a3=in[b+3];
    int s=a0+a1+a2+a3;
    int v=s;
    #pragma unroll
    for(int off=1;off<32;off<<=1){ int u=__shfl_up_sync(~0u,v,off); if(lane>=off) v+=u; }
    __shared__ int wsum[32];
    if(lane==31) wsum[wid]=v;
    __syncthreads();
    if(wid==0){
        int w=wsum[lane];
        #pragma unroll
        for(int off=1;off<32;off<<=1){ int u=__shfl_up_sync(~0u,w,off); if(lane>=off) w+=u; }
        wsum[lane]=w;
    }
    __syncthreads();
    int base=(wid>0)?wsum[wid-1]:0;
    int excl=base+v-s;
    int o0=excl,o1=excl+a0,o2=o1+a1,o3=o2+a2;
    out[b]=o0;out[b+1]=o1;out[b+2]=o2;out[b+3]=o3;
    if(cur){cur[b]=o0;cur[b+1]=o1;cur[b+2]=o2;cur[b+3]=o3;}
    if(MODE==1){
        if(a0) g_midx[o0]=b;
        if(a1) g_midx[o1]=b+1;
        if(a2) g_midx[o2]=b+2;
        if(a3) g_midx[o3]=b+3;
    }
    if(t==1023) out[4096]=o3+a3;
}

// ---- batched SGEMM ----
// epi: 0 plain, 1 relu, 2 C=D+AB, 3 blend, 5 store + Ahv(D=hv), 6 master MLP (store-free)
struct GDesc { const float* A; const float* B; float* C; const float* D;
               const float* E; const float* E2; float* F; int ncol; int epi; };
struct GPack { GDesc d[5]; };
__global__ void k_mgemm(GPack p){
    GDesc g=p.d[blockIdx.z];
    int nblk=g.ncol>>6;
    if((int)blockIdx.x>=nblk) return;
    const int BM=64, BN=64, KB=16;
    __shared__ __align__(16) float As[KB][BM];
    __shared__ __align__(16) float Bs[KB][BN];
    int tid=threadIdx.x;
    int tx=tid%16, ty=tid/16;
    int row0=blockIdx.y*BM, col0=blockIdx.x*BN;
    const float* A=g.A; const float* B=g.B; int ncol=g.ncol;
    float acc[4][4]={};
    for(int kk=0;kk<128;kk+=KB){
        {
            int lin=tid*4; int m=lin/KB; int k=lin%KB;
            float4 a=*(const float4*)&A[(size_t)(row0+m)*128 + kk + k];
            As[k][m]=a.x; As[k+1][m]=a.y; As[k+2][m]=a.z; As[k+3][m]=a.w;
        }
        {
            int lin=tid*4; int k=lin/BN; int n=lin%BN;
            float4 b=*(const float4*)&B[(size_t)(kk+k)*ncol + col0 + n];
            *(float4*)&Bs[k][n]=b;
        }
        __syncthreads();
        #pragma unroll
        for(int k=0;k<KB;k++){
            float4 av=*(const float4*)&As[k][ty*4];
            float4 bv=*(const float4*)&Bs[k][tx*4];
            float a[4]={av.x,av.y,av.z,av.w};
            float bb[4]={bv.x,bv.y,bv.z,bv.w};
            #pragma unroll
            for(int i=0;i<4;i++)
                #pragma unroll
                for(int j=0;j<4;j++) acc[i][j]+=a[i]*bb[j];
        }
        __syncthreads();
    }
    int epi=g.epi;
    if(epi==6){
        float m2w[4];
        #pragma unroll
        for(int j=0;j<4;j++) m2w[j]=g.E[col0+tx*4+j];
        #pragma unroll
        for(int i=0;i<4;i++){
            float part=0.f;
            #pragma unroll
            for(int j=0;j<4;j++){
                float v=fmaxf(acc[i][j]+g.D[col0+tx*4+j],0.f);
                part+=v*m2w[j];
            }
            #pragma unroll
            for(int off=8;off;off>>=1) part+=__shfl_down_sync(~0u,part,off,16);
            if(tx==0){
                int r=row0+ty*4+i;
                float mm=sigf(part+g.E2[0]);
                g_m[r]=mm; g_mask[r]=(mm>0.5f)?1:0; g.F[r]=mm;
            }
        }
        return;
    }
    #pragma unroll
    for(int i=0;i<4;i++){
        int r=row0+ty*4+i;
        float c1=0.f,c2=1.f;
        if(epi==3){ float mm=g_m[r]; float mk=g_mask[r]?mm:0.f; c2=mk; c1=(1.f-mm)+mk; }
        #pragma unroll
        for(int j=0;j<4;j++){
            int col=col0+tx*4+j;
            size_t ci=(size_t)r*ncol+col;
            float v=acc[i][j];
            if(epi==1) v=fmaxf(v,0.f);
            else if(epi==2) v+=g.D[ci];
            else if(epi==3) v=c2*v + c1*g.D[ci];
            g.C[ci]=v;
            if(epi==5 && col<32){
                const float* hv=g.D;
                g_Ahv[(size_t)r*96+col*3+0]=hv[(size_t)r*96+col*3+0]*v;
                g_Ahv[(size_t)r*96+col*3+1]=hv[(size_t)r*96+col*3+1]*v;
                g_Ahv[(size_t)r*96+col*3+2]=hv[(size_t)r*96+col*3+2]*v;
            }
        }
    }
}

__global__ void k_accum1(const float* __restrict__ hv){
    int d=blockIdx.x, t=threadIdx.x;
    float aS=0.f,aV=0.f;
    int vv=t/3, cc=t-vv*3;
    int cnt=g_ecnt[d]; if(cnt>ECAP) cnt=ECAP;
    int base=d*ECAP;
    for(int p=base;p<base+cnt;p++){
        int s=g_esrc[p];
        float ln=g_eln[p];
        aS += ln*g_P1[(size_t)s*128+t];
        if(t<96){
            aV += g_Ahv[s*96+t] + g_edir[p*3+cc]*g_G[s*64+32+vv];
        }
    }
    g_S1[(size_t)d*128+t]=aS;
    if(t<96) g_hlv[d*96+t]=hv[d*96+t]+aV;
}

// att raw logits (compact, gather via midx)
__global__ void k_attn(){
    int nm=g_mscan[Nn];
    int row0=blockIdx.y*128, col0=blockIdx.x*128;
    if(row0>=nm || col0>=nm) return;
    __shared__ __align__(16) float Qs[8][128], Ks[8][128];
    int tid=threadIdx.x;
    int tx=tid%16, ty=tid/16;
    int lin=tid*4; int m=lin/8, kofs=lin%8;
    int qrow=(row0+m<nm)? g_midx[row0+m] : -1;
    int krow=(col0+m<nm)? g_midx[col0+m] : -1;
    float acc[8][8]={};
    for(int kk=0;kk<128;kk+=8){
        float4 q = (qrow>=0) ? *(const float4*)&g_Q   [(size_t)qrow*128+kk+kofs] : make_float4(0,0,0,0);
        Qs[kofs][m]=q.x; Qs[kofs+1][m]=q.y; Qs[kofs+2][m]=q.z; Qs[kofs+3][m]=q.w;
        float4 kv= (krow>=0) ? *(const float4*)&g_Kmat[(size_t)krow*128+kk+kofs] : make_float4(0,0,0,0);
        Ks[kofs][m]=kv.x; Ks[kofs+1][m]=kv.y; Ks[kofs+2][m]=kv.z; Ks[kofs+3][m]=kv.w;
        __syncthreads();
        #pragma unroll
        for(int k2=0;k2<8;k2++){
            float4 a0=*(const float4*)&Qs[k2][ty*8];
            float4 a1=*(const float4*)&Qs[k2][ty*8+4];
            float4 b0=*(const float4*)&Ks[k2][tx*8];
            float4 b1=*(const float4*)&Ks[k2][tx*8+4];
            float a[8]={a0.x,a0.y,a0.z,a0.w,a1.x,a1.y,a1.z,a1.w};
            float b[8]={b0.x,b0.y,b0.z,b0.w,b1.x,b1.y,b1.z,b1.w};
            #pragma unroll
            for(int i=0;i<8;i++)
                #pragma unroll
                for(int j=0;j<8;j++) acc[i][j]+=a[i]*b[j];
        }
        __syncthreads();
    }
    #pragma unroll
    for(int i=0;i<8;i++){
        int r=row0+ty*8+i; if(r>=nm) continue;
        #pragma unroll
        for(int j=0;j<8;j++){
            int c=col0+tx*8+j;
            if(c<nm) g_att[(size_t)r*Nn+c]=acc[i][j]*RSQRT_S;
        }
    }
}

// block-per-row top-8: fast path = 8 lowest-index allowed saturated; exact fallback.
__global__ void k_topk(const float* __restrict__ pos, float* __restrict__ Aout){
    const int T=256;
    int nm=g_mscan[Nn];
    int i=blockIdx.x; if(i>=nm) return;
    int ni=g_midx[i];
    int t=threadIdx.x, lane=t&31, wid=t>>5;

    __shared__ unsigned adjrow[128];
    if(t<128) adjrow[t]=g_adj[(size_t)ni*128+t];
    __syncthreads();

    float B=g_satB;
    int cj[8]; int cn=0;
    for(int j=t;j<nm;j+=T){
        if(j==i) continue;
        int nj=g_midx[j];
        if((adjrow[nj>>5]>>(nj&31))&1u) continue;
        if(g_att[(size_t)i*Nn+j]>=B){ if(cn<8) cj[cn]=j; cn++; }
    }
    __shared__ int scnt;
    if(t==0) scnt=0;
    __syncthreads();
    if(cn) atomicAdd(&scnt,cn);
    __syncthreads();

    __shared__ int selj[8];
    __shared__ float selv[8];
    __shared__ int wj[8]; __shared__ int wt[8]; __shared__ float wvv[8];
    __shared__ int winner;

    if(scnt>=8){
        int hp=0;
        int mycap=(cn<8)?cn:8;
        for(int r=0;r<8;r++){
            int bj=(hp<mycap)?cj[hp]:0x7FFFFFFF;
            int bt=t;
            #pragma unroll
            for(int off=16;off;off>>=1){
                int oj=__shfl_down_sync(~0u,bj,off);
                int ot=__shfl_down_sync(~0u,bt,off);
                if(oj<bj){ bj=oj; bt=ot; }
            }
            if(lane==0){ wj[wid]=bj; wt[wid]=bt; }
            __syncthreads();
            if(t==0){
                int fj=wj[0], ft=wt[0];
                #pragma unroll
                for(int q=1;q<8;q++) if(wj[q]<fj){ fj=wj[q]; ft=wt[q]; }
                selj[r]=fj; winner=ft;
            }
            __syncthreads();
            if(t==winner) hp++;
            __syncthreads();
        }
        if(t<8){
            int nj=g_midx[selj[t]];
            int slot=atomicAdd(&g_nv,1);
            atomicAdd(&g_vcnt[nj],1);
            float vx=pos[ni*3]-pos[nj*3], vy=pos[ni*3+1]-pos[nj*3+1], vz=pos[ni*3+2]-pos[nj*3+2];
            float ln=sqrtf(vx*vx+vy*vy+vz*vz);
            float inv= ln>1e-12f ? 1.f/ln : 0.f;
            g_vsrc[slot]=ni; g_vdst[slot]=nj; g_vln[slot]=ln;
            g_vdir[slot*3]=vx*inv; g_vdir[slot*3+1]=vy*inv; g_vdir[slot*3+2]=vz*inv;
            Aout[(size_t)ni*Nn+nj]=1.0f;
        }
        return;
    }

    // exact sigf lexicographic fallback
    float tv[8]; int tj[8];
    #pragma unroll
    for(int q=0;q<8;q++){ tv[q]=-INFINITY; tj[q]=0x40000000; }
    for(int j=t;j<nm;j+=T){
        if(j==i) continue;
        int nj=g_midx[j];
        if((adjrow[nj>>5]>>(nj&31))&1u) continue;
        float v=sigf(g_att[(size_t)i*Nn+j]);
        if(v>tv[7] || (v==tv[7] && j<tj[7])){
            int p=7;
            while(p>0 && (v>tv[p-1] || (v==tv[p-1]&&j<tj[p-1]))){
                tv[p]=tv[p-1]; tj[p]=tj[p-1]; p--;
            }
            tv[p]=v; tj[p]=j;
        }
    }
    int hp=0;
    for(int r=0;r<8;r++){
        float bv=(hp<8)?tv[hp]:-INFINITY;
        int   bj=(hp<8)?tj[hp]:0x40000000;
        int   bt=t;
        #pragma unroll
        for(int off=16;off;off>>=1){
            float ov=__shfl_down_sync(~0u,bv,off);
            int   oj=__shfl_down_sync(~0u,bj,off);
            int   ot=__shfl_down_sync(~0u,bt,off);
            if(ov>bv || (ov==bv && oj<bj)){ bv=ov;bj=oj;bt=ot; }
        }
        if(lane==0){ wvv[wid]=bv; wj[wid]=bj; wt[wid]=bt; }
        __syncthreads();
        if(t==0){
            float fv=wvv[0]; int fj=wj[0]; int ft=wt[0];
            #pragma unroll
            for(int q=1;q<8;q++){
                if(wvv[q]>fv || (wvv[q]==fv && wj[q]<fj)){ fv=wvv[q]; fj=wj[q]; ft=wt[q]; }
            }
            selv[r]=fv; selj[r]=fj; winner=ft;
        }
        __syncthreads();
        if(t==winner) hp++;
        __syncthreads();
    }
    if(t<8){
        float v=selv[t];
        if(v>0.55f){
            int nj=g_midx[selj[t]];
            int slot=atomicAdd(&g_nv,1);
            atomicAdd(&g_vcnt[nj],1);
            float vx=pos[ni*3]-pos[nj*3], vy=pos[ni*3+1]-pos[nj*3+1], vz=pos[ni*3+2]-pos[nj*3+2];
            float ln=sqrtf(vx*vx+vy*vy+vz*vz);
            float inv= ln>1e-12f ? 1.f/ln : 0.f;
            g_vsrc[slot]=ni; g_vdst[slot]=nj; g_vln[slot]=ln;
            g_vdir[slot*3]=vx*inv; g_vdir[slot*3+1]=vy*inv; g_vdir[slot*3+2]=vz*inv;
            Aout[(size_t)ni*Nn+nj]=1.0f;
        }
    }
}

// vscore: MLP score per virtual edge + CSR insert
__global__ void k_vscore(const float* __restrict__ ba1, const float* __restrict__ Wa2,
                         const float* __restrict__ ba2){
    int slot=blockIdx.x; if(slot>=g_nv) return;
    int t=threadIdx.x;
    int vs=g_vsrc[slot], vd=g_vdst[slot]; float ln=g_vln[slot];
    if(t==0){
        int p=atomicAdd(&g_vcur[vd],1);
        g_vcsr[p]=slot;
    }
    float h=g_U[(size_t)vs*128+t]+g_Vv[(size_t)vd*128+t]+ln*g_w3sum[t]+ba1[t];
    h=fmaxf(h,0.f)*Wa2[t];
    #pragma unroll
    for(int off=16;off;off>>=1) h+=__shfl_down_sync(~0u,h,off);
    __shared__ float ws[4];
    if((t&31)==0) ws[t>>5]=h;
    __syncthreads();
    if(t==0) g_vsc[slot]=ws[0]+ws[1]+ws[2]+ws[3]+ba2[0];
}

// real-edge half of hierarchical accumulation (s2, overlapped)
__global__ void k_accum2r(){
    int d=blockIdx.x, t=threadIdx.x;
    if(!g_mask[d]) return;
    float aS=0.f,aV=0.f;
    int vv=t/3, cc=t-vv*3;
    int cnt=g_ecnt[d]; if(cnt>ECAP) cnt=ECAP;
    int base=d*ECAP;
    for(int p=base;p<base+cnt;p++){
        int s=g_esrc[p];
        if(!g_mask[s]) continue;
        float ln=g_eln[p];
        aS += ln*g_P1[(size_t)s*128+t];
        if(t<96){
            aV += g_Ahv[s*96+t] + g_edir[p*3+cc]*g_G[s*64+32+vv];
        }
    }
    g_S1[(size_t)d*128+t]=aS;
    if(t<96) g_dv[d*96+t]=aV;
}

// virtual-edge add-on with per-dst local softmax
__global__ void k_accum2v(){
    int d=blockIdx.x, t=threadIdx.x, lane=t&31;
    int beg=g_voff[d], end=g_voff[d+1];
    if(beg==end) return;
    __shared__ float smx, sden;
    if(t<32){
        float mx=-INFINITY;
        for(int q=beg+lane;q<end;q+=32) mx=fmaxf(mx,g_vsc[g_vcsr[q]]);
        #pragma unroll
        for(int off=16;off;off>>=1) mx=fmaxf(mx,__shfl_down_sync(~0u,mx,off));
        mx=__shfl_sync(~0u,mx,0);
        float den=0.f;
        for(int q=beg+lane;q<end;q+=32) den+=expf(g_vsc[g_vcsr[q]]-mx);
        #pragma unroll
        for(int off=16;off;off>>=1) den+=__shfl_down_sync(~0u,den,off);
        if(lane==0){ smx=mx; sden=fmaxf(den,1e-9f); }
    }
    __syncthreads();
    float mx=smx, invden=1.f/sden;
    float aS=0.f,aV=0.f;
    int vv=t/3, cc=t-vv*3;
    for(int q=beg;q<end;q++){
        int sl=g_vcsr[q]; int s=g_vsrc[sl];
        float w=expf(g_vsc[sl]-mx)*invden, ln=g_vln[sl];
        aS += ln*w*g_P1[(size_t)s*128+t];
        if(t<96){
            float dir=g_vdir[sl*3+cc]*w;
            aV += g_Ahv[s*96+t] + dir*g_G[s*64+32+vv];
        }
    }
    g_S1[(size_t)d*128+t]+=aS;
    if(t<96) g_dv[d*96+t]+=aV;
}

__global__ void k_finalv(float* __restrict__ out_v){
    int i=blockIdx.x*blockDim.x+threadIdx.x;
    if(i<Nn*96){
        int n=i/96;
        float mm=g_m[n]; float mk=g_mask[n]?mm:0.f;
        out_v[i]=g_hlv[i]*((1.f-mm)+mk)+mk*g_dv[i];
    }
}

extern "C" void kernel_launch(void* const* d_in, const int* in_sizes, int n_in,
                              void* d_out, int out_size){
    const float* h_s =(const float*)d_in[0];
    const float* h_v =(const float*)d_in[1];
    const float* pos =(const float*)d_in[2];
    const int*   ei  =(const int*)  d_in[3];
    const float* W1  =(const float*)d_in[5];
    const float* Wg  =(const float*)d_in[6];
    const float* W2  =(const float*)d_in[7];
    const float* Wm1 =(const float*)d_in[8];
    const float* bm1 =(const float*)d_in[9];
    const float* Wm2 =(const float*)d_in[10];
    const float* bm2 =(const float*)d_in[11];
    const float* Wq  =(const float*)d_in[12];
    const float* Wk  =(const float*)d_in[13];
    const float* Wa1 =(const float*)d_in[14];
    const float* ba1 =(const float*)d_in[15];
    const float* Wa2 =(const float*)d_in[16];
    const float* ba2 =(const float*)d_in[17];

    float *P1,*G,*S1,*HLS,*Q,*KM,*U,*VV,*HLV;
    cudaGetSymbolAddress((void**)&P1, g_P1);
    cudaGetSymbolAddress((void**)&G,  g_G);
    cudaGetSymbolAddress((void**)&S1, g_S1);
    cudaGetSymbolAddress((void**)&HLS,g_hls);
    cudaGetSymbolAddress((void**)&Q,  g_Q);
    cudaGetSymbolAddress((void**)&KM, g_Kmat);
    cudaGetSymbolAddress((void**)&U,  g_U);
    cudaGetSymbolAddress((void**)&VV, g_Vv);
    cudaGetSymbolAddress((void**)&HLV,g_hlv);

    float* out     =(float*)d_out;
    float* out_hfs = out;
    float* out_hfv = out_hfs + (size_t)Nn*Sdim;
    float* out_pos = out_hfv + (size_t)Nn*96;
    float* out_A   = out_pos + (size_t)Nn*3;
    float* out_m   = out_A   + (size_t)Nn*Nn;

    static cudaStream_t s1=0, s2=0;
    static cudaEvent_t evRoot=0, evPrep=0, evZero=0, evHLS=0, evGemmB=0,
                       evScan1=0, evAcc2r=0, evAcc2v=0, evFin=0;
    if(!s1){
        cudaStreamCreateWithFlags(&s1,cudaStreamNonBlocking);
        cudaStreamCreateWithFlags(&s2,cudaStreamNonBlocking);
        cudaEventCreateWithFlags(&evRoot,cudaEventDisableTiming);
        cudaEventCreateWithFlags(&evPrep,cudaEventDisableTiming);
        cudaEventCreateWithFlags(&evZero,cudaEventDisableTiming);
        cudaEventCreateWithFlags(&evHLS,cudaEventDisableTiming);
        cudaEventCreateWithFlags(&evGemmB,cudaEventDisableTiming);
        cudaEventCreateWithFlags(&evScan1,cudaEventDisableTiming);
        cudaEventCreateWithFlags(&evAcc2r,cudaEventDisableTiming);
        cudaEventCreateWithFlags(&evAcc2v,cudaEventDisableTiming);
        cudaEventCreateWithFlags(&evFin,cudaEventDisableTiming);
    }

    cudaEventRecord(evRoot,0);
    cudaStreamWaitEvent(s1,evRoot,0);
    cudaStreamWaitEvent(s2,evRoot,0);

    // s1: adjacency + bucketized edge features (one pass)
    k_initPrep<<<512,256,0,s1>>>(Wa1);
    k_csrfillD<<<(Ee+255)/256,256,0,s1>>>(ei,pos);
    cudaEventRecord(evPrep,s1);

    // s2: zero A_virtual + pos copy
    k_zeroA<<<1024,256,0,s2>>>(out_A,pos,out_pos);
    cudaEventRecord(evZero,s2);

    // main: pass-1 GEMMs
    {
        GPack p{};
        p.d[0]={h_s,W1,P1,nullptr,nullptr,nullptr,nullptr,128,1};
        p.d[1]={h_s,Wg,G, h_v,    nullptr,nullptr,nullptr, 64,5};
        k_mgemm<<<dim3(2,64,2),256>>>(p);
    }
    cudaStreamWaitEvent(0,evPrep,0);
    k_accum1<<<Nn,128>>>(h_v);
    {
        GPack p{};
        p.d[0]={S1,W2,HLS,h_s,nullptr,nullptr,nullptr,128,2};
        k_mgemm<<<dim3(2,64,1),256>>>(p);
    }
    cudaEventRecord(evHLS,0);

    // s1: master MLP (store-free) + mask scan — concurrent with Q/K/U/V pack
    cudaStreamWaitEvent(s1,evHLS,0);
    {
        GPack p{};
        p.d[0]={HLS,Wm1,nullptr,bm1,Wm2,bm2,out_m,64,6};
        k_mgemm<<<dim3(1,64,1),256,0,s1>>>(p);
    }
    k_scan4096<1><<<1,1024,0,s1>>>();
    cudaEventRecord(evScan1,s1);

    // s2: pass-2 backbone GEMMs
    cudaStreamWaitEvent(s2,evHLS,0);
    {
        GPack p{};
        p.d[0]={HLS,W1,P1,nullptr,nullptr,nullptr,nullptr,128,1};
        p.d[1]={HLS,Wg,G, HLV,    nullptr,nullptr,nullptr, 64,5};
        k_mgemm<<<dim3(2,64,2),256,0,s2>>>(p);
    }
    cudaEventRecord(evGemmB,s2);

    // main: Q/K/U/V projections
    {
        GPack p{};
        p.d[0]={HLS,Wq,          Q,  nullptr,nullptr,nullptr,nullptr,128,0};
        p.d[1]={HLS,Wk,          KM, nullptr,nullptr,nullptr,nullptr,128,0};
        p.d[2]={HLS,Wa1,         U,  nullptr,nullptr,nullptr,nullptr,128,0};
        p.d[3]={HLS,Wa1+128*128, VV, nullptr,nullptr,nullptr,nullptr,128,0};
        k_mgemm<<<dim3(2,64,4),256>>>(p);
    }
    cudaStreamWaitEvent(0,evScan1,0);
    k_attn<<<dim3(32,32),256>>>();
    cudaStreamWaitEvent(0,evZero,0);
    k_topk<<<Nn,256>>>(pos,out_A);
    k_scan4096<2><<<1,1024>>>();
    k_vscore<<<Nn*Kk,128>>>(ba1,Wa2,ba2);

    // s2: real-edge accum overlapped with attention chain
    cudaStreamWaitEvent(s2,evScan1,0);
    k_accum2r<<<Nn,128,0,s2>>>();
    cudaEventRecord(evAcc2r,s2);

    // main: virtual add-on, then final GEMM
    cudaStreamWaitEvent(0,evAcc2r,0);
    k_accum2v<<<Nn,128>>>();
    cudaEventRecord(evAcc2v,0);

    // s2: vector blend in parallel with final scalar GEMM
    cudaStreamWaitEvent(s2,evAcc2v,0);
    k_finalv<<<(Nn*96+255)/256,256,0,s2>>>(out_hfv);
    cudaEventRecord(evFin,s2);
    {
        GPack p{};
        p.d[0]={S1,W2,out_hfs,HLS,nullptr,nullptr,nullptr,128,3};
        k_mgemm<<<dim3(2,64,1),256>>>(p);
    }
    cudaStreamWaitEvent(0,evFin,0);
}